// round 13
// baseline (speedup 1.0000x reference)
#include <cuda_runtime.h>
#include <math.h>
#include <stdint.h>

#define NL 12
#define NH 12
#define NC 768
#define NV 50257
#define NVP 50304          // NV padded to multiple of 128
#define NT 1024
#define NB 4
#define ND 64
#define NTOK (NB * NT)     // 4096

// ---- scratch ----
__device__ float g_x[NTOK * NC];
__device__ float g_h[NTOK * NC];
__device__ float g_qkv[NTOK * 3 * NC];
__device__ float g_y[NTOK * NC];
__device__ float g_fc[NTOK * 4 * NC];
__device__ float g_lmT[NC * NVP];    // lm_head transposed [C][Vp], zero-padded

// =====================================================================
// helpers
// =====================================================================
__device__ __forceinline__ uint32_t smem_u32(const void* p) {
    uint32_t a;
    asm("{ .reg .u64 t; cvta.to.shared.u64 t, %1; cvt.u32.u64 %0, t; }"
        : "=r"(a) : "l"(p));
    return a;
}
__device__ __forceinline__ void cpa16(uint32_t dst, const void* src) {
    asm volatile("cp.async.cg.shared.global [%0], [%1], 16;"
                 :: "r"(dst), "l"(src));
}
__device__ __forceinline__ float gelu_f(float u) {
    return 0.5f * u * (1.0f + tanhf(0.7978845608028654f * (u + 0.044715f * u * u * u)));
}

// =====================================================================
// lm_head transpose: [NV][NC] -> [NC][NVP], zero padding
// =====================================================================
__global__ void transpose_lm(const float* __restrict__ src, float* __restrict__ dst) {
    __shared__ float t[32][33];
    int v0 = blockIdx.x * 32, c0 = blockIdx.y * 32;
    int tx = threadIdx.x, ty = threadIdx.y;
    #pragma unroll
    for (int i = ty; i < 32; i += 8)
        t[i][tx] = (v0 + i < NV) ? src[(size_t)(v0 + i) * NC + c0 + tx] : 0.f;
    __syncthreads();
    #pragma unroll
    for (int i = ty; i < 32; i += 8)
        dst[(size_t)(c0 + i) * NVP + v0 + tx] = t[tx][i];
}

// =====================================================================
// embedding
// =====================================================================
__global__ void embed_kernel(const int* __restrict__ idx,
                             const float* __restrict__ wte,
                             const float* __restrict__ wpe,
                             float* __restrict__ x) {
    int row = blockIdx.x;
    int t = row % NT;
    int tok = idx[row];
    const float* we = wte + (size_t)tok * NC;
    const float* wp = wpe + (size_t)t * NC;
    float* out = x + (size_t)row * NC;
    for (int c = threadIdx.x; c < NC; c += blockDim.x)
        out[c] = we[c] + wp[c];
}

// =====================================================================
// layernorm (fp32 out)
// =====================================================================
__global__ void ln_kernel(const float* __restrict__ x,
                          const float* __restrict__ w,
                          const float* __restrict__ b,
                          float* __restrict__ out) {
    int row = blockIdx.x;
    const float* xr = x + (size_t)row * NC;
    __shared__ float red[32];
    int tid = threadIdx.x;
    int nwarp = blockDim.x >> 5;

    float s = 0.f;
    for (int c = tid; c < NC; c += blockDim.x) s += xr[c];
    #pragma unroll
    for (int o = 16; o; o >>= 1) s += __shfl_xor_sync(0xffffffffu, s, o);
    if ((tid & 31) == 0) red[tid >> 5] = s;
    __syncthreads();
    if (tid < 32) {
        float v = (tid < nwarp) ? red[tid] : 0.f;
        #pragma unroll
        for (int o = 16; o; o >>= 1) v += __shfl_xor_sync(0xffffffffu, v, o);
        if (tid == 0) red[0] = v;
    }
    __syncthreads();
    float mu = red[0] * (1.0f / NC);
    __syncthreads();

    float s2 = 0.f;
    for (int c = tid; c < NC; c += blockDim.x) {
        float d = xr[c] - mu;
        s2 += d * d;
    }
    #pragma unroll
    for (int o = 16; o; o >>= 1) s2 += __shfl_xor_sync(0xffffffffu, s2, o);
    if ((tid & 31) == 0) red[tid >> 5] = s2;
    __syncthreads();
    if (tid < 32) {
        float v = (tid < nwarp) ? red[tid] : 0.f;
        #pragma unroll
        for (int o = 16; o; o >>= 1) v += __shfl_xor_sync(0xffffffffu, v, o);
        if (tid == 0) red[0] = v;
    }
    __syncthreads();
    float var = red[0] * (1.0f / NC);
    float rstd = rsqrtf(var + 1e-5f);
    float* outr = out + (size_t)row * NC;
    for (int c = tid; c < NC; c += blockDim.x)
        outr[c] = (xr[c] - mu) * rstd * w[c] + b[c];
}

// =====================================================================
// fp32 SIMT SGEMM (NN): C[M,N] = A[M,K] @ W[K,N] (+bias)(gelu?)(+res)
// 128x128 tile, BK=16, 256 threads, 8x8 microtile, double-buffered,
// B via cp.async, A transpose-on-store. ldb = padded row stride of W.
// Vector C stores only when N % 4 == 0 (lm_head N=50257 -> scalar).
// =====================================================================
#define BM 128
#define BN 128
#define BKS 16

__global__ void __launch_bounds__(256, 2) sgemm_nn(
    const float* __restrict__ A, const float* __restrict__ W,
    const float* __restrict__ bias, const float* __restrict__ res,
    float* __restrict__ C, int M, int N, int ldb, int K, int act)
{
    __shared__ float As[2][BKS][BM];
    __shared__ float Bs[2][BKS][BN];

    int tid = threadIdx.x;
    int lane = tid & 31, warp = tid >> 5;
    int wm = (warp & 3) * 32, wn = (warp >> 2) * 64;
    int lm = lane & 3, ln = lane >> 2;
    int bm = blockIdx.x * BM, bn = blockIdx.y * BN;

    int arow = tid & 127, akq = (tid >> 7) * 8;
    float4 apre0, apre1;

    float c[8][8] = {};
    const int S = K / BKS;

    // ---- prologue: stage 0 ----
    {
        const float* ap = A + (size_t)(bm + arow) * K + akq;
        apre0 = *(const float4*)(ap);
        apre1 = *(const float4*)(ap + 4);
        #pragma unroll
        for (int i = 0; i < 2; i++) {
            int id = tid + i * 256;
            int k = id >> 5, n16 = (id & 31) * 4;
            cpa16(smem_u32(&Bs[0][k][n16]), W + (size_t)k * ldb + bn + n16);
        }
        asm volatile("cp.async.commit_group;");
        #pragma unroll
        for (int i = 0; i < 4; i++) As[0][akq + i][arow] = ((float*)&apre0)[i];
        #pragma unroll
        for (int i = 0; i < 4; i++) As[0][akq + 4 + i][arow] = ((float*)&apre1)[i];
        asm volatile("cp.async.wait_group 0;");
        __syncthreads();
    }

    for (int s = 0; s < S; s++) {
        int cur = s & 1, nxt = cur ^ 1;
        bool more = (s + 1 < S);
        if (more) {
            const float* ap = A + (size_t)(bm + arow) * K + (s + 1) * BKS + akq;
            apre0 = *(const float4*)(ap);
            apre1 = *(const float4*)(ap + 4);
            #pragma unroll
            for (int i = 0; i < 2; i++) {
                int id = tid + i * 256;
                int k = id >> 5, n16 = (id & 31) * 4;
                cpa16(smem_u32(&Bs[nxt][k][n16]),
                      W + (size_t)((s + 1) * BKS + k) * ldb + bn + n16);
            }
            asm volatile("cp.async.commit_group;");
        }

        #pragma unroll
        for (int k = 0; k < BKS; k++) {
            float a[8], b[8];
            *(float4*)&a[0] = *(const float4*)&As[cur][k][wm + lm * 4];
            *(float4*)&a[4] = *(const float4*)&As[cur][k][wm + lm * 4 + 16];
            *(float4*)&b[0] = *(const float4*)&Bs[cur][k][wn + ln * 4];
            *(float4*)&b[4] = *(const float4*)&Bs[cur][k][wn + ln * 4 + 32];
            #pragma unroll
            for (int i = 0; i < 8; i++)
                #pragma unroll
                for (int j = 0; j < 8; j++)
                    c[i][j] = fmaf(a[i], b[j], c[i][j]);
        }

        if (more) {
            #pragma unroll
            for (int i = 0; i < 4; i++) As[nxt][akq + i][arow] = ((float*)&apre0)[i];
            #pragma unroll
            for (int i = 0; i < 4; i++) As[nxt][akq + 4 + i][arow] = ((float*)&apre1)[i];
            asm volatile("cp.async.wait_group 0;");
        }
        __syncthreads();
    }

    // ---- epilogue ----
    bool vec_ok = ((N & 3) == 0);
    #pragma unroll
    for (int i = 0; i < 8; i++) {
        int m = bm + wm + (i >> 2) * 16 + lm * 4 + (i & 3);
        #pragma unroll
        for (int jq = 0; jq < 2; jq++) {
            int n0 = bn + wn + jq * 32 + ln * 4;
            float4 v;
            float* vp = (float*)&v;
            #pragma unroll
            for (int j = 0; j < 4; j++) {
                float u = c[i][jq * 4 + j];
                int col = n0 + j;
                if (bias) u += bias[col];
                if (act) u = gelu_f(u);
                if (res && col < N) u += res[(size_t)m * N + col];
                vp[j] = u;
            }
            if (vec_ok && n0 + 3 < N) {
                *(float4*)&C[(size_t)m * N + n0] = v;
            } else {
                #pragma unroll
                for (int j = 0; j < 4; j++)
                    if (n0 + j < N) C[(size_t)m * N + n0 + j] = vp[j];
            }
        }
    }
}

// =====================================================================
// causal attention (fp32 out)
// =====================================================================
__global__ void attn_kernel(const float* __restrict__ qkv, float* __restrict__ y) {
    int q = blockIdx.x;
    int h = blockIdx.y;
    int b = blockIdx.z;
    int tid = threadIdx.x;

    __shared__ float qs[ND];
    __shared__ float sc[NT];
    __shared__ float red[32];
    __shared__ float yp[2][ND];

    const size_t rs = 3 * NC;
    const float* qptr = qkv + ((size_t)(b * NT + q)) * rs + h * ND;
    if (tid < ND) qs[tid] = qptr[tid];
    __syncthreads();

    const float scale = 0.125f;
    int nk = q + 1;
    const float* kbase = qkv + ((size_t)b * NT) * rs + NC + h * ND;
    for (int k = tid; k < nk; k += blockDim.x) {
        const float* kp = kbase + (size_t)k * rs;
        float d = 0.f;
        #pragma unroll
        for (int i = 0; i < ND; i++) d = fmaf(qs[i], kp[i], d);
        sc[k] = d * scale;
    }
    __syncthreads();

    float m = -1e30f;
    for (int k = tid; k < nk; k += blockDim.x) m = fmaxf(m, sc[k]);
    #pragma unroll
    for (int o = 16; o; o >>= 1) m = fmaxf(m, __shfl_xor_sync(0xffffffffu, m, o));
    if ((tid & 31) == 0) red[tid >> 5] = m;
    __syncthreads();
    if (tid < 32) {
        float v = (tid < (int)(blockDim.x >> 5)) ? red[tid] : -1e30f;
        #pragma unroll
        for (int o = 16; o; o >>= 1) v = fmaxf(v, __shfl_xor_sync(0xffffffffu, v, o));
        if (tid == 0) red[0] = v;
    }
    __syncthreads();
    m = red[0];
    __syncthreads();

    float s = 0.f;
    for (int k = tid; k < nk; k += blockDim.x) {
        float e = __expf(sc[k] - m);
        sc[k] = e;
        s += e;
    }
    #pragma unroll
    for (int o = 16; o; o >>= 1) s += __shfl_xor_sync(0xffffffffu, s, o);
    if ((tid & 31) == 0) red[tid >> 5] = s;
    __syncthreads();
    if (tid < 32) {
        float v = (tid < (int)(blockDim.x >> 5)) ? red[tid] : 0.f;
        #pragma unroll
        for (int o = 16; o; o >>= 1) v += __shfl_xor_sync(0xffffffffu, v, o);
        if (tid == 0) red[0] = v;
    }
    __syncthreads();
    float inv = 1.0f / red[0];

    int part = tid >> 6, d = tid & 63;
    const float* vbase = qkv + ((size_t)b * NT) * rs + 2 * NC + h * ND;
    float acc = 0.f;
    for (int k = part; k < nk; k += 2)
        acc = fmaf(sc[k], vbase[(size_t)k * rs + d], acc);
    yp[part][d] = acc;
    __syncthreads();
    if (tid < ND)
        y[((size_t)(b * NT + q)) * NC + h * ND + tid] = (yp[0][tid] + yp[1][tid]) * inv;
}

// =====================================================================
// launch
// =====================================================================
extern "C" void kernel_launch(void* const* d_in, const int* in_sizes, int n_in,
                              void* d_out, int out_size) {
    const int*   idx    = (const int*)d_in[0];
    const float* wte    = (const float*)d_in[1];
    const float* wpe    = (const float*)d_in[2];
    const float* ln1_w  = (const float*)d_in[3];
    const float* ln1_b  = (const float*)d_in[4];
    const float* ln2_w  = (const float*)d_in[5];
    const float* ln2_b  = (const float*)d_in[6];
    const float* attn_w = (const float*)d_in[7];
    const float* attn_b = (const float*)d_in[8];
    const float* proj_w = (const float*)d_in[9];
    const float* proj_b = (const float*)d_in[10];
    const float* fc_w   = (const float*)d_in[11];
    const float* fc_b   = (const float*)d_in[12];
    const float* fcp_w  = (const float*)d_in[13];
    const float* fcp_b  = (const float*)d_in[14];
    const float* lnf_w  = (const float*)d_in[15];
    const float* lnf_b  = (const float*)d_in[16];
    const float* lmh    = (const float*)d_in[17];
    float* out = (float*)d_out;

    float *x, *h, *qkv, *y, *fc, *lmT;
    cudaGetSymbolAddress((void**)&x, g_x);
    cudaGetSymbolAddress((void**)&h, g_h);
    cudaGetSymbolAddress((void**)&qkv, g_qkv);
    cudaGetSymbolAddress((void**)&y, g_y);
    cudaGetSymbolAddress((void**)&fc, g_fc);
    cudaGetSymbolAddress((void**)&lmT, g_lmT);

    transpose_lm<<<dim3(NVP / 32, NC / 32), dim3(32, 8)>>>(lmh, lmT);

    embed_kernel<<<NTOK, 256>>>(idx, wte, wpe, x);

    for (int l = 0; l < NL; l++) {
        ln_kernel<<<NTOK, 256>>>(x, ln1_w + l * NC, ln1_b + l * NC, h);
        sgemm_nn<<<dim3(NTOK / BM, (3 * NC) / BN), 256>>>(
            h, attn_w + (size_t)l * NC * 3 * NC,
            attn_b + (size_t)l * 3 * NC, nullptr,
            qkv, NTOK, 3 * NC, 3 * NC, NC, 0);
        {
            dim3 grid(NT, NH, NB);
            attn_kernel<<<grid, 128>>>(qkv, y);
        }
        sgemm_nn<<<dim3(NTOK / BM, NC / BN), 256>>>(
            y, proj_w + (size_t)l * NC * NC,
            proj_b + (size_t)l * NC, x,
            x, NTOK, NC, NC, NC, 0);
        ln_kernel<<<NTOK, 256>>>(x, ln2_w + l * NC, ln2_b + l * NC, h);
        sgemm_nn<<<dim3(NTOK / BM, (4 * NC) / BN), 256>>>(
            h, fc_w + (size_t)l * NC * 4 * NC,
            fc_b + (size_t)l * 4 * NC, nullptr,
            fc, NTOK, 4 * NC, 4 * NC, NC, 1);
        sgemm_nn<<<dim3(NTOK / BM, NC / BN), 256>>>(
            fc, fcp_w + (size_t)l * 4 * NC * NC,
            fcp_b + (size_t)l * NC, x,
            x, NTOK, NC, NC, 4 * NC, 0);
    }

    ln_kernel<<<NTOK, 256>>>(x, lnf_w, lnf_b, h);

    // logits = h @ lmT  (N=NV true/odd -> scalar stores, ldb=NVP padded)
    sgemm_nn<<<dim3(NTOK / BM, NVP / BN), 256>>>(
        h, lmT, nullptr, nullptr, out, NTOK, NV, NVP, NC, 0);
}

// round 14
// speedup vs baseline: 2.9502x; 2.9502x over previous
#include <cuda_runtime.h>
#include <math.h>
#include <stdint.h>

#define NL 12
#define NH 12
#define NC 768
#define NV 50257
#define NVP 50304
#define NT 1024
#define NB 4
#define ND 64
#define NTOK (NB * NT)

// ---- scratch ----
__device__ float g_x[NTOK * NC];
__device__ float g_h[NTOK * NC];
__device__ float g_qkv[NTOK * 3 * NC];
__device__ float g_y[NTOK * NC];
__device__ float g_fc[NTOK * 4 * NC];
__device__ float g_lmT[NC * NVP];

// =====================================================================
// helpers
// =====================================================================
__device__ __forceinline__ uint32_t smem_u32(const void* p) {
    uint32_t a;
    asm("{ .reg .u64 t; cvta.to.shared.u64 t, %1; cvt.u32.u64 %0, t; }"
        : "=r"(a) : "l"(p));
    return a;
}
__device__ __forceinline__ void cpa16(uint32_t dst, const void* src) {
    asm volatile("cp.async.cg.shared.global [%0], [%1], 16;"
                 :: "r"(dst), "l"(src));
}
__device__ __forceinline__ float gelu_f(float u) {
    return 0.5f * u * (1.0f + tanhf(0.7978845608028654f * (u + 0.044715f * u * u * u)));
}

// =====================================================================
// lm_head transpose: [NV][NC] -> [NC][NVP], zero padding
// =====================================================================
__global__ void transpose_lm(const float* __restrict__ src, float* __restrict__ dst) {
    __shared__ float t[32][33];
    int v0 = blockIdx.x * 32, c0 = blockIdx.y * 32;
    int tx = threadIdx.x, ty = threadIdx.y;
    #pragma unroll
    for (int i = ty; i < 32; i += 8)
        t[i][tx] = (v0 + i < NV) ? src[(size_t)(v0 + i) * NC + c0 + tx] : 0.f;
    __syncthreads();
    #pragma unroll
    for (int i = ty; i < 32; i += 8)
        dst[(size_t)(c0 + i) * NVP + v0 + tx] = t[tx][i];
}

// =====================================================================
// embedding
// =====================================================================
__global__ void embed_kernel(const int* __restrict__ idx,
                             const float* __restrict__ wte,
                             const float* __restrict__ wpe,
                             float* __restrict__ x) {
    int row = blockIdx.x;
    int t = row % NT;
    int tok = idx[row];
    const float* we = wte + (size_t)tok * NC;
    const float* wp = wpe + (size_t)t * NC;
    float* out = x + (size_t)row * NC;
    for (int c = threadIdx.x; c < NC; c += blockDim.x)
        out[c] = we[c] + wp[c];
}

// =====================================================================
// layernorm
// =====================================================================
__global__ void ln_kernel(const float* __restrict__ x,
                          const float* __restrict__ w,
                          const float* __restrict__ b,
                          float* __restrict__ out) {
    int row = blockIdx.x;
    const float* xr = x + (size_t)row * NC;
    __shared__ float red[32];
    int tid = threadIdx.x;
    int nwarp = blockDim.x >> 5;

    float s = 0.f;
    for (int c = tid; c < NC; c += blockDim.x) s += xr[c];
    #pragma unroll
    for (int o = 16; o; o >>= 1) s += __shfl_xor_sync(0xffffffffu, s, o);
    if ((tid & 31) == 0) red[tid >> 5] = s;
    __syncthreads();
    if (tid < 32) {
        float v = (tid < nwarp) ? red[tid] : 0.f;
        #pragma unroll
        for (int o = 16; o; o >>= 1) v += __shfl_xor_sync(0xffffffffu, v, o);
        if (tid == 0) red[0] = v;
    }
    __syncthreads();
    float mu = red[0] * (1.0f / NC);
    __syncthreads();

    float s2 = 0.f;
    for (int c = tid; c < NC; c += blockDim.x) {
        float d = xr[c] - mu;
        s2 += d * d;
    }
    #pragma unroll
    for (int o = 16; o; o >>= 1) s2 += __shfl_xor_sync(0xffffffffu, s2, o);
    if ((tid & 31) == 0) red[tid >> 5] = s2;
    __syncthreads();
    if (tid < 32) {
        float v = (tid < nwarp) ? red[tid] : 0.f;
        #pragma unroll
        for (int o = 16; o; o >>= 1) v += __shfl_xor_sync(0xffffffffu, v, o);
        if (tid == 0) red[0] = v;
    }
    __syncthreads();
    float var = red[0] * (1.0f / NC);
    float rstd = rsqrtf(var + 1e-5f);
    float* outr = out + (size_t)row * NC;
    for (int c = tid; c < NC; c += blockDim.x)
        outr[c] = (xr[c] - mu) * rstd * w[c] + b[c];
}

// =====================================================================
// fp32 SIMT SGEMM (NN) — unchanged from R13 (measured 46.8 TF/s)
// =====================================================================
#define BM 128
#define BN 128
#define BKS 16

__global__ void __launch_bounds__(256, 2) sgemm_nn(
    const float* __restrict__ A, const float* __restrict__ W,
    const float* __restrict__ bias, const float* __restrict__ res,
    float* __restrict__ C, int M, int N, int ldb, int K, int act)
{
    __shared__ float As[2][BKS][BM];
    __shared__ float Bs[2][BKS][BN];

    int tid = threadIdx.x;
    int lane = tid & 31, warp = tid >> 5;
    int wm = (warp & 3) * 32, wn = (warp >> 2) * 64;
    int lm = lane & 3, ln = lane >> 2;
    int bm = blockIdx.x * BM, bn = blockIdx.y * BN;

    int arow = tid & 127, akq = (tid >> 7) * 8;
    float4 apre0, apre1;

    float c[8][8] = {};
    const int S = K / BKS;

    {
        const float* ap = A + (size_t)(bm + arow) * K + akq;
        apre0 = *(const float4*)(ap);
        apre1 = *(const float4*)(ap + 4);
        #pragma unroll
        for (int i = 0; i < 2; i++) {
            int id = tid + i * 256;
            int k = id >> 5, n16 = (id & 31) * 4;
            cpa16(smem_u32(&Bs[0][k][n16]), W + (size_t)k * ldb + bn + n16);
        }
        asm volatile("cp.async.commit_group;");
        #pragma unroll
        for (int i = 0; i < 4; i++) As[0][akq + i][arow] = ((float*)&apre0)[i];
        #pragma unroll
        for (int i = 0; i < 4; i++) As[0][akq + 4 + i][arow] = ((float*)&apre1)[i];
        asm volatile("cp.async.wait_group 0;");
        __syncthreads();
    }

    for (int s = 0; s < S; s++) {
        int cur = s & 1, nxt = cur ^ 1;
        bool more = (s + 1 < S);
        if (more) {
            const float* ap = A + (size_t)(bm + arow) * K + (s + 1) * BKS + akq;
            apre0 = *(const float4*)(ap);
            apre1 = *(const float4*)(ap + 4);
            #pragma unroll
            for (int i = 0; i < 2; i++) {
                int id = tid + i * 256;
                int k = id >> 5, n16 = (id & 31) * 4;
                cpa16(smem_u32(&Bs[nxt][k][n16]),
                      W + (size_t)((s + 1) * BKS + k) * ldb + bn + n16);
            }
            asm volatile("cp.async.commit_group;");
        }

        #pragma unroll
        for (int k = 0; k < BKS; k++) {
            float a[8], b[8];
            *(float4*)&a[0] = *(const float4*)&As[cur][k][wm + lm * 4];
            *(float4*)&a[4] = *(const float4*)&As[cur][k][wm + lm * 4 + 16];
            *(float4*)&b[0] = *(const float4*)&Bs[cur][k][wn + ln * 4];
            *(float4*)&b[4] = *(const float4*)&Bs[cur][k][wn + ln * 4 + 32];
            #pragma unroll
            for (int i = 0; i < 8; i++)
                #pragma unroll
                for (int j = 0; j < 8; j++)
                    c[i][j] = fmaf(a[i], b[j], c[i][j]);
        }

        if (more) {
            #pragma unroll
            for (int i = 0; i < 4; i++) As[nxt][akq + i][arow] = ((float*)&apre0)[i];
            #pragma unroll
            for (int i = 0; i < 4; i++) As[nxt][akq + 4 + i][arow] = ((float*)&apre1)[i];
            asm volatile("cp.async.wait_group 0;");
        }
        __syncthreads();
    }

    bool vec_ok = ((N & 3) == 0);
    #pragma unroll
    for (int i = 0; i < 8; i++) {
        int m = bm + wm + (i >> 2) * 16 + lm * 4 + (i & 3);
        #pragma unroll
        for (int jq = 0; jq < 2; jq++) {
            int n0 = bn + wn + jq * 32 + ln * 4;
            float4 v;
            float* vp = (float*)&v;
            #pragma unroll
            for (int j = 0; j < 4; j++) {
                float u = c[i][jq * 4 + j];
                int col = n0 + j;
                if (bias) u += bias[col];
                if (act) u = gelu_f(u);
                if (res && col < N) u += res[(size_t)m * N + col];
                vp[j] = u;
            }
            if (vec_ok && n0 + 3 < N) {
                *(float4*)&C[(size_t)m * N + n0] = v;
            } else {
                #pragma unroll
                for (int j = 0; j < 4; j++)
                    if (n0 + j < N) C[(size_t)m * N + n0 + j] = vp[j];
            }
        }
    }
}

// =====================================================================
// FLASH ATTENTION (fp32 SIMT): block = (64-query tile, head, batch).
// K/V tiles of 64 in smem; online softmax; O in registers (16 dims/thr).
// =====================================================================
#define FBQ 64
#define FPITCH 68
#define FSMEM_BYTES (4 * 64 * FPITCH * 4 + 3 * 64 * 4)

__global__ void __launch_bounds__(256) flash_attn(
    const float* __restrict__ qkv, float* __restrict__ y)
{
    extern __shared__ float fs[];
    float* Qt = fs;                    // [d][q]
    float* Kt = Qt + 64 * FPITCH;      // [d][k]
    float* Vs = Kt + 64 * FPITCH;      // [k][d]
    float* Ss = Vs + 64 * FPITCH;      // [q][k]
    float* sm_m = Ss + 64 * FPITCH;
    float* sm_l = sm_m + 64;
    float* sm_a = sm_l + 64;

    int qt = blockIdx.x, h = blockIdx.y, b = blockIdx.z;
    int tid = threadIdx.x, lane = tid & 31, warp = tid >> 5;
    int q0 = qt * FBQ;
    const size_t rs = 3 * NC;
    const float* qbase = qkv + ((size_t)b * NT) * rs + h * ND;
    const float* kbase = qkv + ((size_t)b * NT) * rs + NC + h * ND;
    const float* vbase = qkv + ((size_t)b * NT) * rs + 2 * NC + h * ND;

    float O[16];
    #pragma unroll
    for (int i = 0; i < 16; i++) O[i] = 0.f;
    if (tid < 64) { sm_m[tid] = -1e30f; sm_l[tid] = 0.f; }

    // Q tile -> Qt[d][q]
    #pragma unroll
    for (int i = 0; i < 4; i++) {
        int idx = tid + i * 256;
        int q = idx & 63, c4 = (idx >> 6) * 4;
        float4 v = *(const float4*)(qbase + (size_t)(q0 + q) * rs + c4);
        Qt[(c4 + 0) * FPITCH + q] = v.x;
        Qt[(c4 + 1) * FPITCH + q] = v.y;
        Qt[(c4 + 2) * FPITCH + q] = v.z;
        Qt[(c4 + 3) * FPITCH + q] = v.w;
    }
    __syncthreads();

    int tq = (tid & 15) * 4, tk = (tid >> 4) * 4;
    int pvq = warp * 8 + (lane & 7), dg = lane >> 3;

    for (int kt = 0; kt <= qt; kt++) {
        int kb = kt * FBQ;

        // K tile -> Kt[d][k], V tile -> Vs[k][d]
        #pragma unroll
        for (int i = 0; i < 4; i++) {
            int idx = tid + i * 256;
            int k = idx & 63, c4 = (idx >> 6) * 4;
            float4 v = *(const float4*)(kbase + (size_t)(kb + k) * rs + c4);
            Kt[(c4 + 0) * FPITCH + k] = v.x;
            Kt[(c4 + 1) * FPITCH + k] = v.y;
            Kt[(c4 + 2) * FPITCH + k] = v.z;
            Kt[(c4 + 3) * FPITCH + k] = v.w;
            float4 w = *(const float4*)(vbase + (size_t)(kb + k) * rs + c4);
            *(float4*)&Vs[k * FPITCH + c4] = w;
        }
        __syncthreads();

        // scores: 4x4 per thread
        float s[4][4] = {};
        #pragma unroll 8
        for (int d = 0; d < 64; d++) {
            float4 a4 = *(const float4*)&Qt[d * FPITCH + tq];
            float4 b4 = *(const float4*)&Kt[d * FPITCH + tk];
            const float* aa = (const float*)&a4;
            const float* bb = (const float*)&b4;
            #pragma unroll
            for (int i = 0; i < 4; i++)
                #pragma unroll
                for (int j = 0; j < 4; j++)
                    s[i][j] = fmaf(aa[i], bb[j], s[i][j]);
        }
        bool diag = (kt == qt);
        #pragma unroll
        for (int i = 0; i < 4; i++) {
            float4 v;
            float* vp = (float*)&v;
            #pragma unroll
            for (int j = 0; j < 4; j++) {
                float val = s[i][j] * 0.125f;
                if (diag && (kb + tk + j) > (q0 + tq + i)) val = -1e30f;
                vp[j] = val;
            }
            *(float4*)&Ss[(tq + i) * FPITCH + tk] = v;
        }
        __syncthreads();

        // online softmax: each warp handles 8 rows
        for (int r = 0; r < 8; r++) {
            int q = warp * 8 + r;
            float s0 = Ss[q * FPITCH + lane];
            float s1 = Ss[q * FPITCH + lane + 32];
            float mx = fmaxf(s0, s1);
            #pragma unroll
            for (int o = 16; o; o >>= 1)
                mx = fmaxf(mx, __shfl_xor_sync(0xffffffffu, mx, o));
            float mo = sm_m[q];
            float mn = fmaxf(mo, mx);
            float p0 = __expf(s0 - mn), p1 = __expf(s1 - mn);
            float ps = p0 + p1;
            #pragma unroll
            for (int o = 16; o; o >>= 1)
                ps += __shfl_xor_sync(0xffffffffu, ps, o);
            Ss[q * FPITCH + lane] = p0;
            Ss[q * FPITCH + lane + 32] = p1;
            if (lane == 0) {
                float al = __expf(mo - mn);
                sm_a[q] = al;
                sm_l[q] = sm_l[q] * al + ps;
                sm_m[q] = mn;
            }
        }
        __syncthreads();

        // PV accumulate
        float al = sm_a[pvq];
        #pragma unroll
        for (int i = 0; i < 16; i++) O[i] *= al;
        #pragma unroll 4
        for (int k = 0; k < 64; k++) {
            float p = Ss[pvq * FPITCH + k];
            const float* vr = &Vs[k * FPITCH + dg * 16];
            #pragma unroll
            for (int j = 0; j < 16; j++)
                O[j] = fmaf(p, vr[j], O[j]);
        }
        __syncthreads();
    }

    float inv = 1.0f / sm_l[pvq];
    float* yo = y + ((size_t)(b * NT + q0 + pvq)) * NC + h * ND + dg * 16;
    #pragma unroll
    for (int j = 0; j < 16; j += 4) {
        float4 v = make_float4(O[j] * inv, O[j + 1] * inv,
                               O[j + 2] * inv, O[j + 3] * inv);
        *(float4*)(yo + j) = v;
    }
}

// =====================================================================
// launch
// =====================================================================
extern "C" void kernel_launch(void* const* d_in, const int* in_sizes, int n_in,
                              void* d_out, int out_size) {
    const int*   idx    = (const int*)d_in[0];
    const float* wte    = (const float*)d_in[1];
    const float* wpe    = (const float*)d_in[2];
    const float* ln1_w  = (const float*)d_in[3];
    const float* ln1_b  = (const float*)d_in[4];
    const float* ln2_w  = (const float*)d_in[5];
    const float* ln2_b  = (const float*)d_in[6];
    const float* attn_w = (const float*)d_in[7];
    const float* attn_b = (const float*)d_in[8];
    const float* proj_w = (const float*)d_in[9];
    const float* proj_b = (const float*)d_in[10];
    const float* fc_w   = (const float*)d_in[11];
    const float* fc_b   = (const float*)d_in[12];
    const float* fcp_w  = (const float*)d_in[13];
    const float* fcp_b  = (const float*)d_in[14];
    const float* lnf_w  = (const float*)d_in[15];
    const float* lnf_b  = (const float*)d_in[16];
    const float* lmh    = (const float*)d_in[17];
    float* out = (float*)d_out;

    float *x, *h, *qkv, *y, *fc, *lmT;
    cudaGetSymbolAddress((void**)&x, g_x);
    cudaGetSymbolAddress((void**)&h, g_h);
    cudaGetSymbolAddress((void**)&qkv, g_qkv);
    cudaGetSymbolAddress((void**)&y, g_y);
    cudaGetSymbolAddress((void**)&fc, g_fc);
    cudaGetSymbolAddress((void**)&lmT, g_lmT);

    cudaFuncSetAttribute(flash_attn, cudaFuncAttributeMaxDynamicSharedMemorySize,
                         FSMEM_BYTES);

    transpose_lm<<<dim3(NVP / 32, NC / 32), dim3(32, 8)>>>(lmh, lmT);
    embed_kernel<<<NTOK, 256>>>(idx, wte, wpe, x);

    for (int l = 0; l < NL; l++) {
        ln_kernel<<<NTOK, 256>>>(x, ln1_w + l * NC, ln1_b + l * NC, h);
        sgemm_nn<<<dim3(NTOK / BM, (3 * NC) / BN), 256>>>(
            h, attn_w + (size_t)l * NC * 3 * NC,
            attn_b + (size_t)l * 3 * NC, nullptr,
            qkv, NTOK, 3 * NC, 3 * NC, NC, 0);
        {
            dim3 grid(NT / FBQ, NH, NB);
            flash_attn<<<grid, 256, FSMEM_BYTES>>>(qkv, y);
        }
        sgemm_nn<<<dim3(NTOK / BM, NC / BN), 256>>>(
            y, proj_w + (size_t)l * NC * NC,
            proj_b + (size_t)l * NC, x,
            x, NTOK, NC, NC, NC, 0);
        ln_kernel<<<NTOK, 256>>>(x, ln2_w + l * NC, ln2_b + l * NC, h);
        sgemm_nn<<<dim3(NTOK / BM, (4 * NC) / BN), 256>>>(
            h, fc_w + (size_t)l * NC * 4 * NC,
            fc_b + (size_t)l * 4 * NC, nullptr,
            fc, NTOK, 4 * NC, 4 * NC, NC, 1);
        sgemm_nn<<<dim3(NTOK / BM, NC / BN), 256>>>(
            fc, fcp_w + (size_t)l * 4 * NC * NC,
            fcp_b + (size_t)l * NC, x,
            x, NTOK, NC, NC, 4 * NC, 0);
    }

    ln_kernel<<<NTOK, 256>>>(x, lnf_w, lnf_b, h);

    sgemm_nn<<<dim3(NTOK / BM, NVP / BN), 256>>>(
        h, lmT, nullptr, nullptr, out, NTOK, NV, NVP, NC, 0);
}

// round 15
// speedup vs baseline: 3.2715x; 1.1089x over previous
#include <cuda_runtime.h>
#include <math.h>
#include <stdint.h>

#define NL 12
#define NH 12
#define NC 768
#define NV 50257
#define NVP 50304
#define NT 1024
#define NB 4
#define ND 64
#define NTOK (NB * NT)

// ---- scratch ----
__device__ float g_x[NTOK * NC];
__device__ float g_h[NTOK * NC];
__device__ float g_qkv[NTOK * 3 * NC];
__device__ float g_y[NTOK * NC];
__device__ float g_fc[NTOK * 4 * NC];
__device__ float g_lmT[NC * NVP];

// =====================================================================
// helpers
// =====================================================================
__device__ __forceinline__ uint32_t smem_u32(const void* p) {
    uint32_t a;
    asm("{ .reg .u64 t; cvta.to.shared.u64 t, %1; cvt.u32.u64 %0, t; }"
        : "=r"(a) : "l"(p));
    return a;
}
__device__ __forceinline__ void cpa16(uint32_t dst, const void* src) {
    asm volatile("cp.async.cg.shared.global [%0], [%1], 16;"
                 :: "r"(dst), "l"(src));
}
__device__ __forceinline__ float gelu_f(float u) {
    return 0.5f * u * (1.0f + tanhf(0.7978845608028654f * (u + 0.044715f * u * u * u)));
}

// ---- packed f32x2 (Blackwell FFMA2 path) ----
__device__ __forceinline__ unsigned long long pack2(float x, float y) {
    unsigned long long r;
    asm("mov.b64 %0, {%1, %2};" : "=l"(r) : "f"(x), "f"(y));
    return r;
}
__device__ __forceinline__ void fma2(unsigned long long& c,
                                     unsigned long long a, unsigned long long b) {
    asm("fma.rn.f32x2 %0, %1, %2, %0;" : "+l"(c) : "l"(a), "l"(b));
}
__device__ __forceinline__ void mul2(unsigned long long& d,
                                     unsigned long long a, unsigned long long b) {
    asm("mul.rn.f32x2 %0, %1, %2;" : "=l"(d) : "l"(a), "l"(b));
}
__device__ __forceinline__ void unpack2(unsigned long long v, float& x, float& y) {
    asm("mov.b64 {%0, %1}, %2;" : "=f"(x), "=f"(y) : "l"(v));
}

// =====================================================================
// lm_head transpose: [NV][NC] -> [NC][NVP]
// =====================================================================
__global__ void transpose_lm(const float* __restrict__ src, float* __restrict__ dst) {
    __shared__ float t[32][33];
    int v0 = blockIdx.x * 32, c0 = blockIdx.y * 32;
    int tx = threadIdx.x, ty = threadIdx.y;
    #pragma unroll
    for (int i = ty; i < 32; i += 8)
        t[i][tx] = (v0 + i < NV) ? src[(size_t)(v0 + i) * NC + c0 + tx] : 0.f;
    __syncthreads();
    #pragma unroll
    for (int i = ty; i < 32; i += 8)
        dst[(size_t)(c0 + i) * NVP + v0 + tx] = t[tx][i];
}

// =====================================================================
// embedding
// =====================================================================
__global__ void embed_kernel(const int* __restrict__ idx,
                             const float* __restrict__ wte,
                             const float* __restrict__ wpe,
                             float* __restrict__ x) {
    int row = blockIdx.x;
    int t = row % NT;
    int tok = idx[row];
    const float* we = wte + (size_t)tok * NC;
    const float* wp = wpe + (size_t)t * NC;
    float* out = x + (size_t)row * NC;
    for (int c = threadIdx.x; c < NC; c += blockDim.x)
        out[c] = we[c] + wp[c];
}

// =====================================================================
// layernorm
// =====================================================================
__global__ void ln_kernel(const float* __restrict__ x,
                          const float* __restrict__ w,
                          const float* __restrict__ b,
                          float* __restrict__ out) {
    int row = blockIdx.x;
    const float* xr = x + (size_t)row * NC;
    __shared__ float red[32];
    int tid = threadIdx.x;
    int nwarp = blockDim.x >> 5;

    float s = 0.f;
    for (int c = tid; c < NC; c += blockDim.x) s += xr[c];
    #pragma unroll
    for (int o = 16; o; o >>= 1) s += __shfl_xor_sync(0xffffffffu, s, o);
    if ((tid & 31) == 0) red[tid >> 5] = s;
    __syncthreads();
    if (tid < 32) {
        float v = (tid < nwarp) ? red[tid] : 0.f;
        #pragma unroll
        for (int o = 16; o; o >>= 1) v += __shfl_xor_sync(0xffffffffu, v, o);
        if (tid == 0) red[0] = v;
    }
    __syncthreads();
    float mu = red[0] * (1.0f / NC);
    __syncthreads();

    float s2 = 0.f;
    for (int c = tid; c < NC; c += blockDim.x) {
        float d = xr[c] - mu;
        s2 += d * d;
    }
    #pragma unroll
    for (int o = 16; o; o >>= 1) s2 += __shfl_xor_sync(0xffffffffu, s2, o);
    if ((tid & 31) == 0) red[tid >> 5] = s2;
    __syncthreads();
    if (tid < 32) {
        float v = (tid < nwarp) ? red[tid] : 0.f;
        #pragma unroll
        for (int o = 16; o; o >>= 1) v += __shfl_xor_sync(0xffffffffu, v, o);
        if (tid == 0) red[0] = v;
    }
    __syncthreads();
    float var = red[0] * (1.0f / NC);
    float rstd = rsqrtf(var + 1e-5f);
    float* outr = out + (size_t)row * NC;
    for (int c = tid; c < NC; c += blockDim.x)
        outr[c] = (xr[c] - mu) * rstd * w[c] + b[c];
}

// =====================================================================
// fp32 SIMT SGEMM (NN) with packed FFMA2 inner loop
// =====================================================================
#define BM 128
#define BN 128
#define BKS 16

__global__ void __launch_bounds__(256, 2) sgemm_nn(
    const float* __restrict__ A, const float* __restrict__ W,
    const float* __restrict__ bias, const float* __restrict__ res,
    float* __restrict__ C, int M, int N, int ldb, int K, int act)
{
    __shared__ float As[2][BKS][BM];
    __shared__ float Bs[2][BKS][BN];

    int tid = threadIdx.x;
    int lane = tid & 31, warp = tid >> 5;
    int wm = (warp & 3) * 32, wn = (warp >> 2) * 64;
    int lm = lane & 3, ln = lane >> 2;
    int bm = blockIdx.x * BM, bn = blockIdx.y * BN;

    int arow = tid & 127, akq = (tid >> 7) * 8;
    float4 apre0, apre1;

    unsigned long long c2[8][4];
    #pragma unroll
    for (int i = 0; i < 8; i++)
        #pragma unroll
        for (int j = 0; j < 4; j++) c2[i][j] = 0ULL;

    const int S = K / BKS;

    {
        const float* ap = A + (size_t)(bm + arow) * K + akq;
        apre0 = *(const float4*)(ap);
        apre1 = *(const float4*)(ap + 4);
        #pragma unroll
        for (int i = 0; i < 2; i++) {
            int id = tid + i * 256;
            int k = id >> 5, n16 = (id & 31) * 4;
            cpa16(smem_u32(&Bs[0][k][n16]), W + (size_t)k * ldb + bn + n16);
        }
        asm volatile("cp.async.commit_group;");
        #pragma unroll
        for (int i = 0; i < 4; i++) As[0][akq + i][arow] = ((float*)&apre0)[i];
        #pragma unroll
        for (int i = 0; i < 4; i++) As[0][akq + 4 + i][arow] = ((float*)&apre1)[i];
        asm volatile("cp.async.wait_group 0;");
        __syncthreads();
    }

    for (int s = 0; s < S; s++) {
        int cur = s & 1, nxt = cur ^ 1;
        bool more = (s + 1 < S);
        if (more) {
            const float* ap = A + (size_t)(bm + arow) * K + (s + 1) * BKS + akq;
            apre0 = *(const float4*)(ap);
            apre1 = *(const float4*)(ap + 4);
            #pragma unroll
            for (int i = 0; i < 2; i++) {
                int id = tid + i * 256;
                int k = id >> 5, n16 = (id & 31) * 4;
                cpa16(smem_u32(&Bs[nxt][k][n16]),
                      W + (size_t)((s + 1) * BKS + k) * ldb + bn + n16);
            }
            asm volatile("cp.async.commit_group;");
        }

        #pragma unroll
        for (int k = 0; k < BKS; k++) {
            float a[8], b[8];
            *(float4*)&a[0] = *(const float4*)&As[cur][k][wm + lm * 4];
            *(float4*)&a[4] = *(const float4*)&As[cur][k][wm + lm * 4 + 16];
            *(float4*)&b[0] = *(const float4*)&Bs[cur][k][wn + ln * 4];
            *(float4*)&b[4] = *(const float4*)&Bs[cur][k][wn + ln * 4 + 32];
            unsigned long long b2[4];
            b2[0] = pack2(b[0], b[1]);
            b2[1] = pack2(b[2], b[3]);
            b2[2] = pack2(b[4], b[5]);
            b2[3] = pack2(b[6], b[7]);
            #pragma unroll
            for (int i = 0; i < 8; i++) {
                unsigned long long a2 = pack2(a[i], a[i]);
                #pragma unroll
                for (int j = 0; j < 4; j++)
                    fma2(c2[i][j], a2, b2[j]);
            }
        }

        if (more) {
            #pragma unroll
            for (int i = 0; i < 4; i++) As[nxt][akq + i][arow] = ((float*)&apre0)[i];
            #pragma unroll
            for (int i = 0; i < 4; i++) As[nxt][akq + 4 + i][arow] = ((float*)&apre1)[i];
            asm volatile("cp.async.wait_group 0;");
        }
        __syncthreads();
    }

    // ---- epilogue ----
    bool vec_ok = ((N & 3) == 0);
    #pragma unroll
    for (int i = 0; i < 8; i++) {
        int m = bm + wm + (i >> 2) * 16 + lm * 4 + (i & 3);
        #pragma unroll
        for (int jq = 0; jq < 2; jq++) {
            int n0 = bn + wn + jq * 32 + ln * 4;
            float cv[4];
            unpack2(c2[i][jq * 2 + 0], cv[0], cv[1]);
            unpack2(c2[i][jq * 2 + 1], cv[2], cv[3]);
            float4 v;
            float* vp = (float*)&v;
            #pragma unroll
            for (int j = 0; j < 4; j++) {
                float u = cv[j];
                int col = n0 + j;
                if (bias) u += bias[col];
                if (act) u = gelu_f(u);
                if (res && col < N) u += res[(size_t)m * N + col];
                vp[j] = u;
            }
            if (vec_ok && n0 + 3 < N) {
                *(float4*)&C[(size_t)m * N + n0] = v;
            } else {
                #pragma unroll
                for (int j = 0; j < 4; j++)
                    if (n0 + j < N) C[(size_t)m * N + n0 + j] = vp[j];
            }
        }
    }
}

// =====================================================================
// FLASH ATTENTION (fp32, packed FFMA2 in both hot loops)
// =====================================================================
#define FBQ 64
#define FPITCH 68
#define FSMEM_BYTES (4 * 64 * FPITCH * 4 + 3 * 64 * 4)

__global__ void __launch_bounds__(256) flash_attn(
    const float* __restrict__ qkv, float* __restrict__ y)
{
    extern __shared__ float fs[];
    float* Qt = fs;                    // [d][q]
    float* Kt = Qt + 64 * FPITCH;      // [d][k]
    float* Vs = Kt + 64 * FPITCH;      // [k][d]
    float* Ss = Vs + 64 * FPITCH;      // [q][k]
    float* sm_m = Ss + 64 * FPITCH;
    float* sm_l = sm_m + 64;
    float* sm_a = sm_l + 64;

    int qt = blockIdx.x, h = blockIdx.y, b = blockIdx.z;
    int tid = threadIdx.x, lane = tid & 31, warp = tid >> 5;
    int q0 = qt * FBQ;
    const size_t rs = 3 * NC;
    const float* qbase = qkv + ((size_t)b * NT) * rs + h * ND;
    const float* kbase = qkv + ((size_t)b * NT) * rs + NC + h * ND;
    const float* vbase = qkv + ((size_t)b * NT) * rs + 2 * NC + h * ND;

    unsigned long long O2[8];
    #pragma unroll
    for (int i = 0; i < 8; i++) O2[i] = 0ULL;
    if (tid < 64) { sm_m[tid] = -1e30f; sm_l[tid] = 0.f; }

    #pragma unroll
    for (int i = 0; i < 4; i++) {
        int idx = tid + i * 256;
        int q = idx & 63, c4 = (idx >> 6) * 4;
        float4 v = *(const float4*)(qbase + (size_t)(q0 + q) * rs + c4);
        Qt[(c4 + 0) * FPITCH + q] = v.x;
        Qt[(c4 + 1) * FPITCH + q] = v.y;
        Qt[(c4 + 2) * FPITCH + q] = v.z;
        Qt[(c4 + 3) * FPITCH + q] = v.w;
    }
    __syncthreads();

    int tq = (tid & 15) * 4, tk = (tid >> 4) * 4;
    int pvq = warp * 8 + (lane & 7), dg = lane >> 3;

    for (int kt = 0; kt <= qt; kt++) {
        int kb = kt * FBQ;

        #pragma unroll
        for (int i = 0; i < 4; i++) {
            int idx = tid + i * 256;
            int k = idx & 63, c4 = (idx >> 6) * 4;
            float4 v = *(const float4*)(kbase + (size_t)(kb + k) * rs + c4);
            Kt[(c4 + 0) * FPITCH + k] = v.x;
            Kt[(c4 + 1) * FPITCH + k] = v.y;
            Kt[(c4 + 2) * FPITCH + k] = v.z;
            Kt[(c4 + 3) * FPITCH + k] = v.w;
            float4 w = *(const float4*)(vbase + (size_t)(kb + k) * rs + c4);
            *(float4*)&Vs[k * FPITCH + c4] = w;
        }
        __syncthreads();

        // scores: packed 4x(2x2) per thread
        unsigned long long s2[4][2];
        #pragma unroll
        for (int i = 0; i < 4; i++) { s2[i][0] = 0ULL; s2[i][1] = 0ULL; }
        #pragma unroll 8
        for (int d = 0; d < 64; d++) {
            float4 a4 = *(const float4*)&Qt[d * FPITCH + tq];
            float4 b4 = *(const float4*)&Kt[d * FPITCH + tk];
            const float* aa = (const float*)&a4;
            unsigned long long bb0 = pack2(b4.x, b4.y);
            unsigned long long bb1 = pack2(b4.z, b4.w);
            #pragma unroll
            for (int i = 0; i < 4; i++) {
                unsigned long long a2 = pack2(aa[i], aa[i]);
                fma2(s2[i][0], a2, bb0);
                fma2(s2[i][1], a2, bb1);
            }
        }
        bool diag = (kt == qt);
        #pragma unroll
        for (int i = 0; i < 4; i++) {
            float sv[4];
            unpack2(s2[i][0], sv[0], sv[1]);
            unpack2(s2[i][1], sv[2], sv[3]);
            float4 v;
            float* vp = (float*)&v;
            #pragma unroll
            for (int j = 0; j < 4; j++) {
                float val = sv[j] * 0.125f;
                if (diag && (kb + tk + j) > (q0 + tq + i)) val = -1e30f;
                vp[j] = val;
            }
            *(float4*)&Ss[(tq + i) * FPITCH + tk] = v;
        }
        __syncthreads();

        // online softmax
        for (int r = 0; r < 8; r++) {
            int q = warp * 8 + r;
            float s0 = Ss[q * FPITCH + lane];
            float s1 = Ss[q * FPITCH + lane + 32];
            float mx = fmaxf(s0, s1);
            #pragma unroll
            for (int o = 16; o; o >>= 1)
                mx = fmaxf(mx, __shfl_xor_sync(0xffffffffu, mx, o));
            float mo = sm_m[q];
            float mn = fmaxf(mo, mx);
            float p0 = __expf(s0 - mn), p1 = __expf(s1 - mn);
            float ps = p0 + p1;
            #pragma unroll
            for (int o = 16; o; o >>= 1)
                ps += __shfl_xor_sync(0xffffffffu, ps, o);
            Ss[q * FPITCH + lane] = p0;
            Ss[q * FPITCH + lane + 32] = p1;
            if (lane == 0) {
                float al = __expf(mo - mn);
                sm_a[q] = al;
                sm_l[q] = sm_l[q] * al + ps;
                sm_m[q] = mn;
            }
        }
        __syncthreads();

        // PV accumulate (packed)
        {
            float al = sm_a[pvq];
            unsigned long long al2 = pack2(al, al);
            #pragma unroll
            for (int i = 0; i < 8; i++) mul2(O2[i], O2[i], al2);
        }
        #pragma unroll 4
        for (int k = 0; k < 64; k++) {
            float p = Ss[pvq * FPITCH + k];
            unsigned long long p2 = pack2(p, p);
            const float4* vr = (const float4*)&Vs[k * FPITCH + dg * 16];
            #pragma unroll
            for (int q4 = 0; q4 < 4; q4++) {
                float4 v = vr[q4];
                fma2(O2[q4 * 2 + 0], p2, pack2(v.x, v.y));
                fma2(O2[q4 * 2 + 1], p2, pack2(v.z, v.w));
            }
        }
        __syncthreads();
    }

    float inv = 1.0f / sm_l[pvq];
    float* yo = y + ((size_t)(b * NT + q0 + pvq)) * NC + h * ND + dg * 16;
    #pragma unroll
    for (int j = 0; j < 4; j++) {
        float x0, x1, x2, x3;
        unpack2(O2[j * 2 + 0], x0, x1);
        unpack2(O2[j * 2 + 1], x2, x3);
        float4 v = make_float4(x0 * inv, x1 * inv, x2 * inv, x3 * inv);
        *(float4*)(yo + j * 4) = v;
    }
}

// =====================================================================
// launch
// =====================================================================
extern "C" void kernel_launch(void* const* d_in, const int* in_sizes, int n_in,
                              void* d_out, int out_size) {
    const int*   idx    = (const int*)d_in[0];
    const float* wte    = (const float*)d_in[1];
    const float* wpe    = (const float*)d_in[2];
    const float* ln1_w  = (const float*)d_in[3];
    const float* ln1_b  = (const float*)d_in[4];
    const float* ln2_w  = (const float*)d_in[5];
    const float* ln2_b  = (const float*)d_in[6];
    const float* attn_w = (const float*)d_in[7];
    const float* attn_b = (const float*)d_in[8];
    const float* proj_w = (const float*)d_in[9];
    const float* proj_b = (const float*)d_in[10];
    const float* fc_w   = (const float*)d_in[11];
    const float* fc_b   = (const float*)d_in[12];
    const float* fcp_w  = (const float*)d_in[13];
    const float* fcp_b  = (const float*)d_in[14];
    const float* lnf_w  = (const float*)d_in[15];
    const float* lnf_b  = (const float*)d_in[16];
    const float* lmh    = (const float*)d_in[17];
    float* out = (float*)d_out;

    float *x, *h, *qkv, *y, *fc, *lmT;
    cudaGetSymbolAddress((void**)&x, g_x);
    cudaGetSymbolAddress((void**)&h, g_h);
    cudaGetSymbolAddress((void**)&qkv, g_qkv);
    cudaGetSymbolAddress((void**)&y, g_y);
    cudaGetSymbolAddress((void**)&fc, g_fc);
    cudaGetSymbolAddress((void**)&lmT, g_lmT);

    cudaFuncSetAttribute(flash_attn, cudaFuncAttributeMaxDynamicSharedMemorySize,
                         FSMEM_BYTES);

    transpose_lm<<<dim3(NVP / 32, NC / 32), dim3(32, 8)>>>(lmh, lmT);
    embed_kernel<<<NTOK, 256>>>(idx, wte, wpe, x);

    for (int l = 0; l < NL; l++) {
        ln_kernel<<<NTOK, 256>>>(x, ln1_w + l * NC, ln1_b + l * NC, h);
        sgemm_nn<<<dim3(NTOK / BM, (3 * NC) / BN), 256>>>(
            h, attn_w + (size_t)l * NC * 3 * NC,
            attn_b + (size_t)l * 3 * NC, nullptr,
            qkv, NTOK, 3 * NC, 3 * NC, NC, 0);
        {
            dim3 grid(NT / FBQ, NH, NB);
            flash_attn<<<grid, 256, FSMEM_BYTES>>>(qkv, y);
        }
        sgemm_nn<<<dim3(NTOK / BM, NC / BN), 256>>>(
            y, proj_w + (size_t)l * NC * NC,
            proj_b + (size_t)l * NC, x,
            x, NTOK, NC, NC, NC, 0);
        ln_kernel<<<NTOK, 256>>>(x, ln2_w + l * NC, ln2_b + l * NC, h);
        sgemm_nn<<<dim3(NTOK / BM, (4 * NC) / BN), 256>>>(
            h, fc_w + (size_t)l * NC * 4 * NC,
            fc_b + (size_t)l * 4 * NC, nullptr,
            fc, NTOK, 4 * NC, 4 * NC, NC, 1);
        sgemm_nn<<<dim3(NTOK / BM, NC / BN), 256>>>(
            fc, fcp_w + (size_t)l * 4 * NC * NC,
            fcp_b + (size_t)l * NC, x,
            x, NTOK, NC, NC, 4 * NC, 0);
    }

    ln_kernel<<<NTOK, 256>>>(x, lnf_w, lnf_b, h);

    sgemm_nn<<<dim3(NTOK / BM, NVP / BN), 256>>>(
        h, lmT, nullptr, nullptr, out, NTOK, NV, NVP, NC, 0);
}